// round 3
// baseline (speedup 1.0000x reference)
#include <cuda_runtime.h>
#include <cuda_bf16.h>

// Problem constants (fixed by the dataset)
constexpr int B  = 8;
constexpr int T  = 256;
constexpr int U  = 64;
constexpr int U1 = U + 1;   // 65
constexpr int V  = 1024;

#define NEGV (-1e30f)

// Scratch (allocation-free rule: __device__ globals)
__device__ float g_blank[B * T * U1];   // lp[...,0]
__device__ float g_emit [B * T * U];    // lp at label, masked
__device__ float g_ll   [B];

// ---------------------------------------------------------------------------
// Kernel 1: one warp per (b,t,u) row of V=1024. Register-resident row
// (8 x float4 per lane), warp max + warp sum-exp, then emit 2 scalars.
// HBM-bound: 545 MB read.
// ---------------------------------------------------------------------------
__global__ void __launch_bounds__(256) softmax_kernel(
    const float* __restrict__ logits,
    const int*   __restrict__ labels,
    const int*   __restrict__ y_len)
{
    int gw   = (blockIdx.x * blockDim.x + threadIdx.x) >> 5;   // global warp = row
    int lane = threadIdx.x & 31;
    if (gw >= B * T * U1) return;

    const float4* row = reinterpret_cast<const float4*>(logits) + (size_t)gw * (V / 4);

    float4 v[8];
    float mx = -3.4e38f;
#pragma unroll
    for (int k = 0; k < 8; k++) {
        v[k] = row[k * 32 + lane];                       // coalesced 128B/warp
        mx = fmaxf(mx, fmaxf(fmaxf(v[k].x, v[k].y), fmaxf(v[k].z, v[k].w)));
    }
#pragma unroll
    for (int o = 16; o; o >>= 1) mx = fmaxf(mx, __shfl_xor_sync(0xffffffffu, mx, o));

    float s = 0.f;
#pragma unroll
    for (int k = 0; k < 8; k++) {
        s += __expf(v[k].x - mx) + __expf(v[k].y - mx)
           + __expf(v[k].z - mx) + __expf(v[k].w - mx);
    }
#pragma unroll
    for (int o = 16; o; o >>= 1) s += __shfl_xor_sync(0xffffffffu, s, o);

    float lse = mx + __logf(s);

    if (lane == 0) {
        g_blank[gw] = v[0].x - lse;                      // element 0 lives in lane 0
        int u = gw % U1;
        if (u < U) {
            int b = gw / (T * U1);
            int t = (gw / U1) % T;
            float e = NEGV;
            if (u < y_len[b]) {
                int l = labels[b * U + u];
                e = __ldg(logits + (size_t)gw * V + l) - lse;   // L1 hit (just loaded)
            }
            g_emit[(b * T + t) * U + u] = e;
        }
    }
}

// ---------------------------------------------------------------------------
// Kernel 2: per-batch alpha recurrence via anti-diagonal wavefront.
// alpha[t][u] = logaddexp(alpha[t-1][u] + blank[t-1][u],
//                         alpha[t][u-1] + emit[t][u-1])
// blank/emit staged in dynamic smem (133 KB) so each diagonal step is
// LDS-latency only. One __syncthreads per diagonal; double-buffered diag.
// ---------------------------------------------------------------------------
__device__ __forceinline__ float ladd(float x, float y)
{
    float m = fmaxf(x, y);
    float d = fabsf(x - y);
    return m + log1pf(__expf(-d));
}

extern __shared__ float sh[];

__global__ void __launch_bounds__(96) alpha_kernel(
    const int* __restrict__ f_len,
    const int* __restrict__ y_len)
{
    int b   = blockIdx.x;
    int tid = threadIdx.x;

    float* sb   = sh;                  // [T][U1] blank
    float* se   = sh + T * U1;         // [T][U]  emit
    float* a0   = se + T * U;          // [U1] alpha row t=0
    float* dbuf = a0 + U1;             // 2 x [U1] diagonal double buffer

    for (int i = tid; i < T * U1; i += 96) sb[i] = g_blank[b * T * U1 + i];
    for (int i = tid; i < T * U;  i += 96) se[i] = g_emit [b * T * U  + i];
    __syncthreads();

    if (tid == 0) {                    // alpha[0][u] = cumsum emit[0][0..u-1]
        float c = 0.f;
        a0[0] = 0.f;
        for (int u = 0; u < U; u++) { c += se[u]; a0[u + 1] = c; }
    }
    __syncthreads();

    int tl = f_len[b] - 1;             // last valid frame (127..255)
    int yl = y_len[b];                 // label length    (32..64)
    int dmax = tl + yl;
    int u = tid;                       // only tid <= 64 ever active

    for (int d = 0; d <= dmax; d++) {
        float* cur  = dbuf + (d & 1) * U1;
        float* prev = dbuf + ((d + 1) & 1) * U1;
        if (u <= d && u <= U && (d - u) <= tl) {
            int t = d - u;
            float val;
            if (t == 0)      val = a0[u];
            else if (u == 0) val = prev[0] + sb[(t - 1) * U1];
            else             val = ladd(prev[u]     + sb[(t - 1) * U1 + u],
                                        prev[u - 1] + se[t * U + (u - 1)]);
            cur[u] = val;
            if (t == tl && u == yl)
                g_ll[b] = val + sb[tl * U1 + yl];
        }
        __syncthreads();
    }
}

// ---------------------------------------------------------------------------
// Kernel 3: out = -mean(ll)
// ---------------------------------------------------------------------------
__global__ void finish_kernel(float* __restrict__ out)
{
    float s = 0.f;
    if (threadIdx.x < B) s = g_ll[threadIdx.x];
#pragma unroll
    for (int o = 16; o; o >>= 1) s += __shfl_xor_sync(0xffffffffu, s, o);
    if (threadIdx.x == 0) out[0] = -s * (1.0f / B);
}

// ---------------------------------------------------------------------------
extern "C" void kernel_launch(void* const* d_in, const int* in_sizes, int n_in,
                              void* d_out, int out_size)
{
    const float* logits = (const float*)d_in[0];
    const int*   labels = (const int*)  d_in[1];
    const int*   f_len  = (const int*)  d_in[2];
    const int*   y_len  = (const int*)  d_in[3];

    int rows = B * T * U1;             // 133,120 warps
    int blocks = (rows * 32 + 255) / 256;
    softmax_kernel<<<blocks, 256>>>(logits, labels, y_len);

    size_t smem = (size_t)(T * U1 + T * U + U1 + 2 * U1) * sizeof(float); // ~133 KB
    cudaFuncSetAttribute(alpha_kernel,
                         cudaFuncAttributeMaxDynamicSharedMemorySize, (int)smem);
    alpha_kernel<<<B, 96, smem>>>(f_len, y_len);

    finish_kernel<<<1, 32>>>((float*)d_out);
}

// round 4
// speedup vs baseline: 1.6259x; 1.6259x over previous
#include <cuda_runtime.h>
#include <cuda_bf16.h>

constexpr int B  = 8;
constexpr int T  = 256;
constexpr int U  = 64;
constexpr int U1 = U + 1;   // 65
constexpr int V  = 1024;

#define NEGV (-1e30f)

// Scratch (allocation-free rule: __device__ globals).
// TRANSPOSED layout [b][u][t] so the alpha wavefront reads advance by +1 in t
// (2-way max bank conflicts instead of 32-way with [t][u]).
__device__ float g_blank[B * U1 * T];
__device__ float g_emit [B * U  * T];
__device__ float g_ll   [B];

// ---------------------------------------------------------------------------
// Kernel 1: one warp per (b,t,u) row of V=1024. Register-resident row
// (8 x float4 per lane), warp max + warp sum-exp. HBM-bound: 545 MB read.
// ---------------------------------------------------------------------------
__global__ void __launch_bounds__(256) softmax_kernel(
    const float* __restrict__ logits,
    const int*   __restrict__ labels,
    const int*   __restrict__ y_len)
{
    int gw   = (blockIdx.x * blockDim.x + threadIdx.x) >> 5;   // global warp = row
    int lane = threadIdx.x & 31;
    if (gw >= B * T * U1) return;

    const float4* row = reinterpret_cast<const float4*>(logits) + (size_t)gw * (V / 4);

    float4 v[8];
    float mx = -3.4e38f;
#pragma unroll
    for (int k = 0; k < 8; k++) {
        v[k] = row[k * 32 + lane];                       // coalesced 128B/warp
        mx = fmaxf(mx, fmaxf(fmaxf(v[k].x, v[k].y), fmaxf(v[k].z, v[k].w)));
    }
#pragma unroll
    for (int o = 16; o; o >>= 1) mx = fmaxf(mx, __shfl_xor_sync(0xffffffffu, mx, o));

    float s = 0.f;
#pragma unroll
    for (int k = 0; k < 8; k++) {
        s += __expf(v[k].x - mx) + __expf(v[k].y - mx)
           + __expf(v[k].z - mx) + __expf(v[k].w - mx);
    }
#pragma unroll
    for (int o = 16; o; o >>= 1) s += __shfl_xor_sync(0xffffffffu, s, o);

    float lse = mx + __logf(s);

    if (lane == 0) {
        int b = gw / (T * U1);
        int r = gw % (T * U1);
        int t = r / U1;
        int u = r % U1;
        g_blank[(b * U1 + u) * T + t] = v[0].x - lse;    // element 0 lives in lane 0
        if (u < U) {
            float e = NEGV;
            if (u < y_len[b]) {
                int l = labels[b * U + u];
                e = __ldg(logits + (size_t)gw * V + l) - lse;   // L1 hit (just loaded)
            }
            g_emit[(b * U + u) * T + t] = e;
        }
    }
}

// ---------------------------------------------------------------------------
// Kernel 2: per-batch alpha recurrence, warp-synchronous wavefront.
// One warp per batch. Lane l owns u = {2l, 2l+1}; lane 31 also owns u = 64.
// Per diagonal: ONE __shfl_up (prev[2l-1] from lane l-1), no __syncthreads,
// alpha state entirely in registers. blank/emit staged in smem [u][T].
//
//   alpha[t][u] = ladd(alpha[t-1][u] + blank[t-1][u],
//                      alpha[t][u-1] + emit[t][u-1])
//   alpha[0][u] = cumsum(emit[0][0..u-1])   (warp exclusive scan, one-time)
//
// Garbage cells (t > t_last, u not yet active) are computed unmasked: their
// smem indices provably stay inside the staged block, they remain finite, and
// they never feed any cell with t <= t_last.
// ---------------------------------------------------------------------------
__device__ __forceinline__ float ladd(float x, float y)
{
    float m = fmaxf(x, y);
    return m + __logf(1.0f + __expf(-fabsf(x - y)));
}

__global__ void __launch_bounds__(128) alpha_kernel(
    const int* __restrict__ f_len,
    const int* __restrict__ y_len)
{
    extern __shared__ float sh[];
    float* sb = sh;            // [U1][T] blank
    float* se = sh + U1 * T;   // [U][T]  emit

    int b   = blockIdx.x;
    int tid = threadIdx.x;

    // Stage both arrays into smem (coalesced float4).
    {
        const float4* srcb = reinterpret_cast<const float4*>(g_blank + b * U1 * T);
        float4*       dstb = reinterpret_cast<float4*>(sb);
        for (int i = tid; i < U1 * T / 4; i += 128) dstb[i] = srcb[i];
        const float4* srce = reinterpret_cast<const float4*>(g_emit + b * U * T);
        float4*       dste = reinterpret_cast<float4*>(se);
        for (int i = tid; i < U * T / 4; i += 128) dste[i] = srce[i];
    }
    __syncthreads();
    if (tid >= 32) return;

    int lane = tid;
    int tl = f_len[b] - 1;     // last valid frame (127..255)
    int yl = y_len[b];         // label length    (32..64)

    const int uA = 2 * lane;
    const int uB = 2 * lane + 1;
    const int uC = 64;         // only meaningful on lane 31

    // alpha[0][u]: exclusive scan of emit[0][u] pairs.
    float p = se[uA * T];      // emit[0][2l]
    float q = se[uB * T];      // emit[0][2l+1]
    float S = p + q;
#pragma unroll
    for (int o = 1; o < 32; o <<= 1) {
        float t = __shfl_up_sync(0xffffffffu, S, o);
        if (lane >= o) S += t;
    }
    float Sexcl = __shfl_up_sync(0xffffffffu, S, 1);
    if (lane == 0) Sexcl = 0.f;
    float a0A = Sexcl;                              // alpha0[2l]
    float a0B = Sexcl + p;                          // alpha0[2l+1]
    float a0C = __shfl_sync(0xffffffffu, S, 31);    // alpha0[64] = total

    float aA = NEGV, aB = NEGV, aC = NEGV;
    int dmax = tl + yl;

    for (int d = 0; d <= dmax; d++) {
        float oA = aA, oB = aB, oC = aC;
        float pm1 = __shfl_up_sync(0xffffffffu, oB, 1);   // prev[2l-1]

        int tA = d - uA, tB = d - uB, tC = d - uC;

        // smem reads (addresses are alpha-independent -> off the serial chain)
        int ibA = uA * T + tA - 1; ibA = ibA < 0 ? 0 : ibA;   // lane0,d=0 only
        float sbA = sb[ibA];
        float sbB = sb[uB * T + tB - 1];
        float sbC = sb[uC * T + tC - 1];
        float seA = (uA == 0) ? NEGV : se[(uA - 1) * T + tA]; // m[0] = NEG
        float seB = se[(uB - 1) * T + tB];
        float seC = se[(uC - 1) * T + tC];

        float nA = ladd(oA + sbA, pm1 + seA);
        float nB = ladd(oB + sbB, oA  + seB);
        float nC = ladd(oC + sbC, oB  + seC);

        nA = (d == uA) ? a0A : nA;   // t==0 init row
        nB = (d == uB) ? a0B : nB;
        nC = (d == uC) ? a0C : nC;

        aA = (d < uA) ? oA : nA;     // not yet active: hold
        aB = (d < uB) ? oB : nB;
        aC = (d < uC) ? oC : nC;
    }

    // Final: ll = alpha[tl][yl] + blank[tl][yl]; exactly one lane owns u=yl.
    float res = 0.f; bool hit = false;
    if (uA == yl)                       { res = aA; hit = true; }
    else if (uB == yl)                  { res = aB; hit = true; }
    else if (lane == 31 && yl == 64)    { res = aC; hit = true; }
    if (hit) g_ll[b] = res + sb[yl * T + tl];
}

// ---------------------------------------------------------------------------
// Kernel 3: out = -mean(ll)
// ---------------------------------------------------------------------------
__global__ void finish_kernel(float* __restrict__ out)
{
    float s = 0.f;
    if (threadIdx.x < B) s = g_ll[threadIdx.x];
#pragma unroll
    for (int o = 16; o; o >>= 1) s += __shfl_xor_sync(0xffffffffu, s, o);
    if (threadIdx.x == 0) out[0] = -s * (1.0f / B);
}

// ---------------------------------------------------------------------------
extern "C" void kernel_launch(void* const* d_in, const int* in_sizes, int n_in,
                              void* d_out, int out_size)
{
    const float* logits = (const float*)d_in[0];
    const int*   labels = (const int*)  d_in[1];
    const int*   f_len  = (const int*)  d_in[2];
    const int*   y_len  = (const int*)  d_in[3];

    int rows = B * T * U1;             // 133,120 warps
    int blocks = (rows * 32 + 255) / 256;
    softmax_kernel<<<blocks, 256>>>(logits, labels, y_len);

    size_t smem = (size_t)(U1 * T + U * T) * sizeof(float);   // 132,096 B
    cudaFuncSetAttribute(alpha_kernel,
                         cudaFuncAttributeMaxDynamicSharedMemorySize, (int)smem);
    alpha_kernel<<<B, 128, smem>>>(f_len, y_len);

    finish_kernel<<<1, 32>>>((float*)d_out);
}